// round 15
// baseline (speedup 1.0000x reference)
#include <cuda_runtime.h>
#include <cuda_bf16.h>
#include <cstdint>
#include <cstddef>

#define B_DIM 64
#define N_DIM 1024
#define D_DIM 256
#define T_DIM 13
#define C_DIM 2
#define KX (C_DIM * T_DIM)          // 26
#define NROWS (B_DIM * N_DIM)        // 65536

// c2 = 2*rank - 255 per (row, d), exact in bf16. 32 MB static scratch.
__device__ __nv_bfloat16 g_c2[(size_t)NROWS * D_DIM];
// per-tile LN partials: [b][rowblock][slot][128 rows][{sum,sq}]  (4 MB)
__device__ float g_part[(size_t)B_DIM * 8 * 8 * 256];
__device__ float g_mu[NROWS];
__device__ float g_rstd[NROWS];

#define SKW(i) ((i) + ((i) >> 5))
#define SBUF_LEN 264

// ---------------------------------------------------------------------------
// Dual bitonic sort of two 256-key sets (2x ILP). 8 keys/lane, p = lane*8+s.
// ---------------------------------------------------------------------------
__device__ __forceinline__ void bitonic256_x2(unsigned a0[8], unsigned a1[8],
                                              int lane)
{
#pragma unroll
    for (int ks = 1; ks <= 8; ks++) {
        const int k = 1 << ks;
#pragma unroll
        for (int js = ks - 1; js >= 0; js--) {
            const int j = 1 << js;
            if (j >= 8) {
                const int jl = j >> 3;
                bool up = ((lane & (k >> 3)) == 0);
                bool keepmin = (((lane & jl) == 0) == up);
#pragma unroll
                for (int s = 0; s < 8; s++) {
                    unsigned o0 = __shfl_xor_sync(0xffffffffu, a0[s], jl);
                    unsigned o1 = __shfl_xor_sync(0xffffffffu, a1[s], jl);
                    unsigned mn0 = a0[s] < o0 ? a0[s] : o0;
                    unsigned mx0 = a0[s] < o0 ? o0 : a0[s];
                    unsigned mn1 = a1[s] < o1 ? a1[s] : o1;
                    unsigned mx1 = a1[s] < o1 ? o1 : a1[s];
                    a0[s] = keepmin ? mn0 : mx0;
                    a1[s] = keepmin ? mn1 : mx1;
                }
            } else {
#pragma unroll
                for (int s = 0; s < 8; s++) {
                    if ((s & j) == 0) {
                        int a = s, b2 = s | j;
                        int p = (lane << 3) | a;
                        bool up = ((p & k) == 0);
                        unsigned x0 = a0[a], y0 = a0[b2];
                        unsigned x1 = a1[a], y1 = a1[b2];
                        unsigned mn0 = x0 < y0 ? x0 : y0;
                        unsigned mx0 = x0 < y0 ? y0 : x0;
                        unsigned mn1 = x1 < y1 ? x1 : y1;
                        unsigned mx1 = x1 < y1 ? y1 : x1;
                        a0[a]  = up ? mn0 : mx0;
                        a0[b2] = up ? mx0 : mn0;
                        a1[a]  = up ? mn1 : mx1;
                        a1[b2] = up ? mx1 : mn1;
                    }
                }
            }
        }
    }
}

// ---------------------------------------------------------------------------
// K1: conv + LayerNorm(D) + rank (dual bitonic + skewed binary search),
// 2 rows/warp. Output bf16 c2 = 2*rank - 255.
// ---------------------------------------------------------------------------
__global__ __launch_bounds__(256) void k1_rank(
    const float* __restrict__ x, const float* __restrict__ w,
    const float* __restrict__ cb, const float* __restrict__ tg,
    const float* __restrict__ tb)
{
    __shared__ float wst[KX * D_DIM];
    __shared__ float scb[D_DIM];
    __shared__ float sxs[16][KX + 2];
    __shared__ unsigned sortbuf[16][SBUF_LEN];

    int tid = threadIdx.x;
#pragma unroll
    for (int k = 0; k < KX; k++) wst[k * D_DIM + tid] = w[tid * KX + k];
    scb[tid] = cb[tid];

    int warp = tid >> 5, lane = tid & 31;
    int row0 = blockIdx.x * 16 + warp * 2;

#pragma unroll
    for (int r = 0; r < 2; r++) {
        int row = row0 + r;
        int b = row >> 10, n = row & 1023;
        if (lane < KX) {
            int c = lane / T_DIM, t = lane - c * T_DIM;
            sxs[warp * 2 + r][lane] =
                x[(((size_t)b * C_DIM + c) * N_DIM + n) * T_DIM + t];
        }
    }
    __syncthreads();

    float gv[8], bv[8];
#pragma unroll
    for (int s = 0; s < 8; s++) { gv[s] = tg[s * 32 + lane]; bv[s] = tb[s * 32 + lane]; }

    float e0[8], e1[8];
#pragma unroll
    for (int s = 0; s < 8; s++) { e0[s] = scb[s * 32 + lane]; e1[s] = e0[s]; }
#pragma unroll
    for (int k = 0; k < KX; k++) {
        float x0 = sxs[warp * 2][k], x1 = sxs[warp * 2 + 1][k];
#pragma unroll
        for (int s = 0; s < 8; s++) {
            float wv = wst[k * D_DIM + s * 32 + lane];
            e0[s] += x0 * wv;
            e1[s] += x1 * wv;
        }
    }

    float s0 = 0.f, q0 = 0.f, s1 = 0.f, q1 = 0.f;
#pragma unroll
    for (int s = 0; s < 8; s++) {
        s0 += e0[s]; q0 += e0[s] * e0[s];
        s1 += e1[s]; q1 += e1[s] * e1[s];
    }
#pragma unroll
    for (int o = 16; o > 0; o >>= 1) {
        s0 += __shfl_xor_sync(0xffffffffu, s0, o);
        q0 += __shfl_xor_sync(0xffffffffu, q0, o);
        s1 += __shfl_xor_sync(0xffffffffu, s1, o);
        q1 += __shfl_xor_sync(0xffffffffu, q1, o);
    }
    float mu0 = s0 * (1.0f / D_DIM);
    float rstd0 = rsqrtf(q0 * (1.0f / D_DIM) - mu0 * mu0 + 1e-5f);
    float mu1 = s1 * (1.0f / D_DIM);
    float rstd1 = rsqrtf(q1 * (1.0f / D_DIM) - mu1 * mu1 + 1e-5f);

    unsigned orig0[8], orig1[8], it0[8], it1[8];
#pragma unroll
    for (int s = 0; s < 8; s++) {
        float z0 = (e0[s] - mu0) * rstd0 * gv[s] + bv[s];
        float z1 = (e1[s] - mu1) * rstd1 * gv[s] + bv[s];
        unsigned u0 = __float_as_uint(z0);
        unsigned u1 = __float_as_uint(z1);
        orig0[s] = (u0 & 0x80000000u) ? ~u0 : (u0 | 0x80000000u);
        orig1[s] = (u1 & 0x80000000u) ? ~u1 : (u1 | 0x80000000u);
        it0[s] = orig0[s];
        it1[s] = orig1[s];
    }

    bitonic256_x2(it0, it1, lane);

    unsigned* sb0 = sortbuf[warp * 2];
    unsigned* sb1 = sortbuf[warp * 2 + 1];
#pragma unroll
    for (int s = 0; s < 8; s++) {
        sb0[SKW(lane * 8 + s)] = it0[s];
        sb1[SKW(lane * 8 + s)] = it1[s];
    }
    __syncwarp();

    unsigned lo0[8], lo1[8];
#pragma unroll
    for (int s = 0; s < 8; s++) { lo0[s] = 0; lo1[s] = 0; }
#pragma unroll
    for (int wstep = 128; wstep > 0; wstep >>= 1) {
#pragma unroll
        for (int s = 0; s < 8; s++) {
            if (sb0[SKW(lo0[s] + wstep - 1)] < orig0[s]) lo0[s] += wstep;
            if (sb1[SKW(lo1[s] + wstep - 1)] < orig1[s]) lo1[s] += wstep;
        }
    }
    __syncwarp();

    __nv_bfloat16* st0 = (__nv_bfloat16*)sb0;
    __nv_bfloat16* st1 = (__nv_bfloat16*)sb1;
#pragma unroll
    for (int s = 0; s < 8; s++) {
        st0[s * 32 + lane] = __float2bfloat16((float)(2 * (int)lo0[s] - 255));
        st1[s * 32 + lane] = __float2bfloat16((float)(2 * (int)lo1[s] - 255));
    }
    __syncwarp();

    size_t base = (size_t)row0 * D_DIM;
    *(uint4*)(g_c2 + base + lane * 8) = ((const uint4*)st0)[lane];
    *(uint4*)(g_c2 + base + D_DIM + lane * 8) = ((const uint4*)st1)[lane];
}

// ---------------------------------------------------------------------------
// Shared bf16 HMMA mainloop (2 CTAs/SM, double-buffered K=64 chunks,
// pitch 72). acc[4][4][4] f32, exact. Ends WITHOUT trailing sync.
// ---------------------------------------------------------------------------
#define LDB 72    // chunk pitch in bf16 (144B rows: LDSM + cp.async CF)
#define TSP 132   // transpose staging pitch (floats)
#define SMEM_K2 73728
#define SMEM_K2B 77824              // + 4KB param region (sst) past tiles
#define ADJ_SCALE (0.25f / (1398080.0f + 1e-8f))

__constant__ int IT_MAP[36] = {0,0,0,0,0,0,0,0, 1,1,1,1,1,1,1, 2,2,2,2,2,2,
                               3,3,3,3,3, 4,4,4,4, 5,5,5, 6,6, 7};
__constant__ int JT_MAP[36] = {0,1,2,3,4,5,6,7, 1,2,3,4,5,6,7, 2,3,4,5,6,7,
                               3,4,5,6,7, 4,5,6,7, 5,6,7, 6,7, 7};

__device__ __forceinline__ unsigned sptr(const void* p) {
    return (unsigned)__cvta_generic_to_shared(p);
}
__device__ __forceinline__ void cpasync16(unsigned dst, const void* src) {
    asm volatile("cp.async.cg.shared.global [%0], [%1], 16;\n"
                 :: "r"(dst), "l"(src));
}
__device__ __forceinline__ void cpcommit() {
    asm volatile("cp.async.commit_group;\n");
}
template <int N>
__device__ __forceinline__ void cpwait() {
    asm volatile("cp.async.wait_group %0;\n" :: "n"(N));
}
__device__ __forceinline__ void ldm4(unsigned& r0, unsigned& r1, unsigned& r2,
                                     unsigned& r3, unsigned a) {
    asm volatile("ldmatrix.sync.aligned.m8n8.x4.shared.b16 {%0,%1,%2,%3}, [%4];\n"
                 : "=r"(r0), "=r"(r1), "=r"(r2), "=r"(r3) : "r"(a));
}
__device__ __forceinline__ void mma16816(float* d, const unsigned* a,
                                         unsigned b0, unsigned b1) {
    asm volatile(
        "mma.sync.aligned.m16n8k16.row.col.f32.bf16.bf16.f32 "
        "{%0,%1,%2,%3},{%4,%5,%6,%7},{%8,%9},{%0,%1,%2,%3};\n"
        : "+f"(d[0]), "+f"(d[1]), "+f"(d[2]), "+f"(d[3])
        : "r"(a[0]), "r"(a[1]), "r"(a[2]), "r"(a[3]), "r"(b0), "r"(b1));
}

__device__ __forceinline__ void k2_mainloop(
    int b, int it, int jt, bool diag, __nv_bfloat16* smem, float acc[4][4][4])
{
    __nv_bfloat16* Ast[2] = { smem, smem + 128 * LDB };
    __nv_bfloat16* Bst[2] = { diag ? Ast[0] : smem + 2 * 128 * LDB,
                              diag ? Ast[1] : smem + 3 * 128 * LDB };

    const __nv_bfloat16* Ag = g_c2 + ((size_t)b * N_DIM + it * 128) * D_DIM;
    const __nv_bfloat16* Bg = g_c2 + ((size_t)b * N_DIM + jt * 128) * D_DIM;

    int tid = threadIdx.x;

#define LOAD_CHUNK(c, Ad, Bd)                                                  \
    do {                                                                       \
        _Pragma("unroll")                                                      \
        for (int i = 0; i < 4; i++) {                                          \
            int idx = tid + i * 256;                                           \
            int r = idx >> 3, line = idx & 7;                                  \
            int off = (c) * 64 + line * 8;                                     \
            cpasync16(sptr((Ad) + r * LDB + line * 8), Ag + r * D_DIM + off);  \
        }                                                                      \
        if (!diag) {                                                           \
            _Pragma("unroll")                                                  \
            for (int i = 0; i < 4; i++) {                                      \
                int idx = tid + i * 256;                                       \
                int r = idx >> 3, line = idx & 7;                              \
                int off = (c) * 64 + line * 8;                                 \
                cpasync16(sptr((Bd) + r * LDB + line * 8), Bg + r * D_DIM + off); \
            }                                                                  \
        }                                                                      \
        cpcommit();                                                            \
    } while (0)

    LOAD_CHUNK(0, Ast[0], Bst[0]);
    LOAD_CHUNK(1, Ast[1], Bst[1]);

    int wid = tid >> 5, lane = tid & 31;
    int wm = (wid >> 2) * 64, wn = (wid & 3) * 32;

#pragma unroll
    for (int mf = 0; mf < 4; mf++)
#pragma unroll
        for (int nf = 0; nf < 4; nf++)
#pragma unroll
            for (int r = 0; r < 4; r++) acc[mf][nf][r] = 0.f;

#pragma unroll
    for (int c = 0; c < 4; c++) {
        if (c < 3) cpwait<1>(); else cpwait<0>();
        __syncthreads();
        __nv_bfloat16* Asb = Ast[c & 1];
        __nv_bfloat16* Bsb = Bst[c & 1];
        unsigned aaddr[4];
#pragma unroll
        for (int mf = 0; mf < 4; mf++)
            aaddr[mf] = sptr(Asb + (wm + mf * 16 + (lane & 15)) * LDB
                             + ((lane >> 4) << 3));
        unsigned baddr = sptr(Bsb + (wn + lane) * LDB);

#pragma unroll
        for (int kk = 0; kk < 64; kk += 16) {
            unsigned a[4][4];
#pragma unroll
            for (int mf = 0; mf < 4; mf++)
                ldm4(a[mf][0], a[mf][1], a[mf][2], a[mf][3], aaddr[mf] + 2 * kk);
            unsigned bl[4], bh[4];
            ldm4(bl[0], bl[1], bl[2], bl[3], baddr + 2 * kk);
            ldm4(bh[0], bh[1], bh[2], bh[3], baddr + 2 * kk + 16);
#pragma unroll
            for (int mf = 0; mf < 4; mf++)
#pragma unroll
                for (int nf = 0; nf < 4; nf++)
                    mma16816(acc[mf][nf], a[mf], bl[nf], bh[nf]);
        }
        if (c + 2 < 4) {
            __syncthreads();
            LOAD_CHUNK(c + 2, Asb, Bsb);
        }
    }
#undef LOAD_CHUNK
}

__device__ __forceinline__ float adjv(float a) {
    return fabsf(a) * ADJ_SCALE;
}

// ---------------------------------------------------------------------------
// K2a: mainloop + per-tile row/col (sum, sumsq) LN partials. No adj write.
// ---------------------------------------------------------------------------
__global__ __launch_bounds__(256, 2) void k2a_stats()
{
    extern __shared__ __nv_bfloat16 smem[];
    int b = blockIdx.z, tt = blockIdx.x;
    int it = IT_MAP[tt], jt = JT_MAP[tt];
    bool diag = (it == jt);

    float acc[4][4][4];
    k2_mainloop(b, it, jt, diag, smem, acc);
    __syncthreads();    // all warps done with tiles; smem reusable

    int tid = threadIdx.x, wid = tid >> 5, lane = tid & 31;
    int wm = (wid >> 2) * 64, wn = (wid & 3) * 32;
    float* sred = (float*)smem;                 // [128][4 wn-groups][2]

    // ---- row partials ----
    float rs[8], rq[8];
#pragma unroll
    for (int mf = 0; mf < 4; mf++) {
        float a0 = 0.f, c0 = 0.f, a1 = 0.f, c1 = 0.f;
#pragma unroll
        for (int nf = 0; nf < 4; nf++) {
            float v0 = adjv(acc[mf][nf][0]), v1 = adjv(acc[mf][nf][1]);
            float v2 = adjv(acc[mf][nf][2]), v3 = adjv(acc[mf][nf][3]);
            a0 += v0 + v1; c0 += v0 * v0 + v1 * v1;
            a1 += v2 + v3; c1 += v2 * v2 + v3 * v3;
        }
        rs[mf * 2] = a0; rq[mf * 2] = c0;
        rs[mf * 2 + 1] = a1; rq[mf * 2 + 1] = c1;
    }
#pragma unroll
    for (int o = 1; o <= 2; o <<= 1)
#pragma unroll
        for (int m = 0; m < 8; m++) {
            rs[m] += __shfl_xor_sync(0xffffffffu, rs[m], o);
            rq[m] += __shfl_xor_sync(0xffffffffu, rq[m], o);
        }
    if ((lane & 3) == 0) {
#pragma unroll
        for (int m = 0; m < 8; m++) {
            int r = wm + (m >> 1) * 16 + (m & 1) * 8 + (lane >> 2);
            sred[(r * 4 + (wid & 3)) * 2]     = rs[m];
            sred[(r * 4 + (wid & 3)) * 2 + 1] = rq[m];
        }
    }
    __syncthreads();
    if (tid < 128) {
        float S = 0.f, Q = 0.f;
#pragma unroll
        for (int g = 0; g < 4; g++) {
            S += sred[(tid * 4 + g) * 2];
            Q += sred[(tid * 4 + g) * 2 + 1];
        }
        float2 v; v.x = S; v.y = Q;
        *(float2*)(g_part + (((size_t)b * 8 + it) * 8 + jt) * 256 + tid * 2) = v;
    }
    if (diag) return;
    __syncthreads();

    // ---- col partials ----
    float* scol = sred;
    float cs[8], cq[8];
#pragma unroll
    for (int nf = 0; nf < 4; nf++) {
        float a0 = 0.f, c0 = 0.f, a1 = 0.f, c1 = 0.f;
#pragma unroll
        for (int mf = 0; mf < 4; mf++) {
            float v0 = adjv(acc[mf][nf][0]), v1 = adjv(acc[mf][nf][1]);
            float v2 = adjv(acc[mf][nf][2]), v3 = adjv(acc[mf][nf][3]);
            a0 += v0 + v2; c0 += v0 * v0 + v2 * v2;
            a1 += v1 + v3; c1 += v1 * v1 + v3 * v3;
        }
        cs[nf * 2] = a0; cq[nf * 2] = c0;
        cs[nf * 2 + 1] = a1; cq[nf * 2 + 1] = c1;
    }
#pragma unroll
    for (int o = 4; o <= 16; o <<= 1)
#pragma unroll
        for (int n = 0; n < 8; n++) {
            cs[n] += __shfl_xor_sync(0xffffffffu, cs[n], o);
            cq[n] += __shfl_xor_sync(0xffffffffu, cq[n], o);
        }
    if (lane < 4) {
#pragma unroll
        for (int n = 0; n < 8; n++) {
            int c = wn + lane * 2 + (n >> 1) * 8 + (n & 1);
            scol[(c * 2 + (wid >> 2)) * 2]     = cs[n];
            scol[(c * 2 + (wid >> 2)) * 2 + 1] = cq[n];
        }
    }
    __syncthreads();
    if (tid < 128) {
        float S = scol[(tid * 2) * 2]     + scol[(tid * 2 + 1) * 2];
        float Q = scol[(tid * 2) * 2 + 1] + scol[(tid * 2 + 1) * 2 + 1];
        float2 v; v.x = S; v.y = Q;
        *(float2*)(g_part + (((size_t)b * 8 + jt) * 8 + it) * 256 + tid * 2) = v;
    }
}

// ---------------------------------------------------------------------------
// K_stats: finalize mu/rstd per output row from the 8 partial slots.
// ---------------------------------------------------------------------------
__global__ void k_stats()
{
    int row = blockIdx.x * 256 + threadIdx.x;
    int blk = row >> 7, rowin = row & 127;
    const float* p = g_part + (size_t)blk * 8 * 256 + rowin * 2;
    float S = 0.f, Q = 0.f;
#pragma unroll
    for (int s = 0; s < 8; s++) { S += p[s * 256]; Q += p[s * 256 + 1]; }
    float mu = S * (1.0f / N_DIM);
    float var = Q * (1.0f / N_DIM) - mu * mu;
    g_mu[row] = mu;
    g_rstd[row] = rsqrtf(var + 1e-5f);
}

// ---------------------------------------------------------------------------
// K2b: identical mainloop (same f32 S) + fused LN + ReLU + single write.
// LN params preloaded before the mainloop (sst past the tile buffers).
// ---------------------------------------------------------------------------
__global__ __launch_bounds__(256, 2) void k2b_write(
    float* __restrict__ out, const float* __restrict__ sg,
    const float* __restrict__ sb)
{
    extern __shared__ __nv_bfloat16 smem[];
    int b = blockIdx.z, tt = blockIdx.x;
    int it = IT_MAP[tt], jt = JT_MAP[tt];
    bool diag = (it == jt);
    int tid = threadIdx.x;

    float* sst = (float*)((char*)smem + SMEM_K2);      // 1024 floats
    if (tid < 128) {
        int iG = it * 128 + tid, jG = jt * 128 + tid;
        int base = b * N_DIM;
        sst[0 * 128 + tid] = g_mu[base + iG];
        sst[1 * 128 + tid] = g_rstd[base + iG];
        sst[2 * 128 + tid] = sg[jG];
        sst[3 * 128 + tid] = sb[jG];
        sst[4 * 128 + tid] = g_mu[base + jG];
        sst[5 * 128 + tid] = g_rstd[base + jG];
        sst[6 * 128 + tid] = sg[iG];
        sst[7 * 128 + tid] = sb[iG];
    }

    float acc[4][4][4];
    k2_mainloop(b, it, jt, diag, smem, acc);
    __syncthreads();    // tiles done; sst visible; ts region reusable

    int wid = tid >> 5, lane = tid & 31;
    int wm = (wid >> 2) * 64, wn = (wid & 3) * 32;
    int il = wm + (lane >> 2), jl = wn + (lane & 3) * 2;

    float* ts = (float*)smem;                          // [128][TSP] staging
    float* ob = out + (size_t)b * N_DIM * N_DIM;

    // direct tile: rows i (stats), cols j (affine)
#pragma unroll
    for (int mf = 0; mf < 4; mf++) {
        int i0 = il + mf * 16;
        float mA = sst[i0], rA = sst[128 + i0];
        float mB = sst[i0 + 8], rB = sst[128 + i0 + 8];
#pragma unroll
        for (int nf = 0; nf < 4; nf++) {
            int j0 = jl + nf * 8;
            float gj0 = sst[256 + j0], bj0 = sst[384 + j0];
            float gj1 = sst[256 + j0 + 1], bj1 = sst[384 + j0 + 1];
            float2 v0, v1;
            v0.x = fmaxf((adjv(acc[mf][nf][0]) - mA) * rA * gj0 + bj0, 0.f);
            v0.y = fmaxf((adjv(acc[mf][nf][1]) - mA) * rA * gj1 + bj1, 0.f);
            v1.x = fmaxf((adjv(acc[mf][nf][2]) - mB) * rB * gj0 + bj0, 0.f);
            v1.y = fmaxf((adjv(acc[mf][nf][3]) - mB) * rB * gj1 + bj1, 0.f);
            size_t iG0 = (size_t)(it * 128 + i0) * N_DIM + jt * 128 + j0;
            *(float2*)(ob + iG0) = v0;
            *(float2*)(ob + iG0 + 8 * N_DIM) = v1;
        }
    }

    if (diag) return;

    // mirror tile: rows j (stats), cols i (affine); normalize, stage, write
#pragma unroll
    for (int mf = 0; mf < 4; mf++) {
        int i0 = il + mf * 16;
        float gi0 = sst[768 + i0], bi0 = sst[896 + i0];
        float gi8 = sst[768 + i0 + 8], bi8 = sst[896 + i0 + 8];
#pragma unroll
        for (int nf = 0; nf < 4; nf++) {
            int j0 = jl + nf * 8;
            float mJ0 = sst[512 + j0], rJ0 = sst[640 + j0];
            float mJ1 = sst[512 + j0 + 1], rJ1 = sst[640 + j0 + 1];
            ts[(j0    ) * TSP + i0    ] =
                fmaxf((adjv(acc[mf][nf][0]) - mJ0) * rJ0 * gi0 + bi0, 0.f);
            ts[(j0 + 1) * TSP + i0    ] =
                fmaxf((adjv(acc[mf][nf][1]) - mJ1) * rJ1 * gi0 + bi0, 0.f);
            ts[(j0    ) * TSP + i0 + 8] =
                fmaxf((adjv(acc[mf][nf][2]) - mJ0) * rJ0 * gi8 + bi8, 0.f);
            ts[(j0 + 1) * TSP + i0 + 8] =
                fmaxf((adjv(acc[mf][nf][3]) - mJ1) * rJ1 * gi8 + bi8, 0.f);
        }
    }
    __syncthreads();

#pragma unroll
    for (int pass = 0; pass < 16; pass++) {
        int r = (tid >> 5) + pass * 8;
        int c4 = (tid & 31) * 4;
        float4 v = *(float4*)&ts[r * TSP + c4];
        *(float4*)(ob + (size_t)(jt * 128 + r) * N_DIM + it * 128 + c4) = v;
    }
}

// ---------------------------------------------------------------------------
extern "C" void kernel_launch(void* const* d_in, const int* in_sizes, int n_in,
                              void* d_out, int out_size)
{
    (void)in_sizes; (void)n_in; (void)out_size;
    const float* x        = (const float*)d_in[0];
    const float* conv_w   = (const float*)d_in[1];
    const float* conv_b   = (const float*)d_in[2];
    const float* time_g   = (const float*)d_in[3];
    const float* time_b   = (const float*)d_in[4];
    const float* static_g = (const float*)d_in[5];
    const float* static_b = (const float*)d_in[6];
    float* out = (float*)d_out;

    // Max-shared carveout: lets 4 x 46KB k1 CTAs reside per SM (vs 2 at the
    // default tier), doubling k1 occupancy. Harmless for the k2 kernels.
    cudaFuncSetAttribute(k1_rank,
                         cudaFuncAttributePreferredSharedMemoryCarveout,
                         cudaSharedmemCarveoutMaxShared);
    cudaFuncSetAttribute(k2a_stats, cudaFuncAttributeMaxDynamicSharedMemorySize,
                         SMEM_K2);
    cudaFuncSetAttribute(k2b_write, cudaFuncAttributeMaxDynamicSharedMemorySize,
                         SMEM_K2B);

    k1_rank<<<NROWS / 16, 256>>>(x, conv_w, conv_b, time_g, time_b);

    dim3 g2(36, 1, 64);
    k2a_stats<<<g2, 256, SMEM_K2>>>();
    k_stats<<<NROWS / 256, 256>>>();
    k2b_write<<<g2, 256, SMEM_K2B>>>(out, static_g, static_b);
}

// round 16
// speedup vs baseline: 1.0295x; 1.0295x over previous
#include <cuda_runtime.h>
#include <cuda_bf16.h>
#include <cstdint>
#include <cstddef>

#define B_DIM 64
#define N_DIM 1024
#define D_DIM 256
#define T_DIM 13
#define C_DIM 2
#define KX (C_DIM * T_DIM)          // 26
#define NROWS (B_DIM * N_DIM)        // 65536

// c2 = 2*rank - 255 per (row, d), exact in bf16. 32 MB static scratch.
__device__ __nv_bfloat16 g_c2[(size_t)NROWS * D_DIM];
// per-tile LN partials: [b][rowblock][slot][128 rows][{sum,sq}]  (4 MB)
__device__ float g_part[(size_t)B_DIM * 8 * 8 * 256];
__device__ float g_mu[NROWS];
__device__ float g_rstd[NROWS];

#define SKW(i) ((i) + ((i) >> 5))
#define SBUF_LEN 264

// ---------------------------------------------------------------------------
// Dual bitonic sort of two 256-key sets (2x ILP). 8 keys/lane, p = lane*8+s.
// ---------------------------------------------------------------------------
__device__ __forceinline__ void bitonic256_x2(unsigned a0[8], unsigned a1[8],
                                              int lane)
{
#pragma unroll
    for (int ks = 1; ks <= 8; ks++) {
        const int k = 1 << ks;
#pragma unroll
        for (int js = ks - 1; js >= 0; js--) {
            const int j = 1 << js;
            if (j >= 8) {
                const int jl = j >> 3;
                bool up = ((lane & (k >> 3)) == 0);
                bool keepmin = (((lane & jl) == 0) == up);
#pragma unroll
                for (int s = 0; s < 8; s++) {
                    unsigned o0 = __shfl_xor_sync(0xffffffffu, a0[s], jl);
                    unsigned o1 = __shfl_xor_sync(0xffffffffu, a1[s], jl);
                    unsigned mn0 = a0[s] < o0 ? a0[s] : o0;
                    unsigned mx0 = a0[s] < o0 ? o0 : a0[s];
                    unsigned mn1 = a1[s] < o1 ? a1[s] : o1;
                    unsigned mx1 = a1[s] < o1 ? o1 : a1[s];
                    a0[s] = keepmin ? mn0 : mx0;
                    a1[s] = keepmin ? mn1 : mx1;
                }
            } else {
#pragma unroll
                for (int s = 0; s < 8; s++) {
                    if ((s & j) == 0) {
                        int a = s, b2 = s | j;
                        int p = (lane << 3) | a;
                        bool up = ((p & k) == 0);
                        unsigned x0 = a0[a], y0 = a0[b2];
                        unsigned x1 = a1[a], y1 = a1[b2];
                        unsigned mn0 = x0 < y0 ? x0 : y0;
                        unsigned mx0 = x0 < y0 ? y0 : x0;
                        unsigned mn1 = x1 < y1 ? x1 : y1;
                        unsigned mx1 = x1 < y1 ? y1 : x1;
                        a0[a]  = up ? mn0 : mx0;
                        a0[b2] = up ? mx0 : mn0;
                        a1[a]  = up ? mn1 : mx1;
                        a1[b2] = up ? mx1 : mn1;
                    }
                }
            }
        }
    }
}

// ---------------------------------------------------------------------------
// K1: conv + LayerNorm(D) + rank (dual bitonic + skewed binary search),
// 2 rows/warp. Output bf16 c2 = 2*rank - 255.
// ---------------------------------------------------------------------------
__global__ __launch_bounds__(256) void k1_rank(
    const float* __restrict__ x, const float* __restrict__ w,
    const float* __restrict__ cb, const float* __restrict__ tg,
    const float* __restrict__ tb)
{
    __shared__ float wst[KX * D_DIM];
    __shared__ float scb[D_DIM];
    __shared__ float sxs[16][KX + 2];
    __shared__ unsigned sortbuf[16][SBUF_LEN];

    int tid = threadIdx.x;
#pragma unroll
    for (int k = 0; k < KX; k++) wst[k * D_DIM + tid] = w[tid * KX + k];
    scb[tid] = cb[tid];

    int warp = tid >> 5, lane = tid & 31;
    int row0 = blockIdx.x * 16 + warp * 2;

#pragma unroll
    for (int r = 0; r < 2; r++) {
        int row = row0 + r;
        int b = row >> 10, n = row & 1023;
        if (lane < KX) {
            int c = lane / T_DIM, t = lane - c * T_DIM;
            sxs[warp * 2 + r][lane] =
                x[(((size_t)b * C_DIM + c) * N_DIM + n) * T_DIM + t];
        }
    }
    __syncthreads();

    float gv[8], bv[8];
#pragma unroll
    for (int s = 0; s < 8; s++) { gv[s] = tg[s * 32 + lane]; bv[s] = tb[s * 32 + lane]; }

    float e0[8], e1[8];
#pragma unroll
    for (int s = 0; s < 8; s++) { e0[s] = scb[s * 32 + lane]; e1[s] = e0[s]; }
#pragma unroll
    for (int k = 0; k < KX; k++) {
        float x0 = sxs[warp * 2][k], x1 = sxs[warp * 2 + 1][k];
#pragma unroll
        for (int s = 0; s < 8; s++) {
            float wv = wst[k * D_DIM + s * 32 + lane];
            e0[s] += x0 * wv;
            e1[s] += x1 * wv;
        }
    }

    float s0 = 0.f, q0 = 0.f, s1 = 0.f, q1 = 0.f;
#pragma unroll
    for (int s = 0; s < 8; s++) {
        s0 += e0[s]; q0 += e0[s] * e0[s];
        s1 += e1[s]; q1 += e1[s] * e1[s];
    }
#pragma unroll
    for (int o = 16; o > 0; o >>= 1) {
        s0 += __shfl_xor_sync(0xffffffffu, s0, o);
        q0 += __shfl_xor_sync(0xffffffffu, q0, o);
        s1 += __shfl_xor_sync(0xffffffffu, s1, o);
        q1 += __shfl_xor_sync(0xffffffffu, q1, o);
    }
    float mu0 = s0 * (1.0f / D_DIM);
    float rstd0 = rsqrtf(q0 * (1.0f / D_DIM) - mu0 * mu0 + 1e-5f);
    float mu1 = s1 * (1.0f / D_DIM);
    float rstd1 = rsqrtf(q1 * (1.0f / D_DIM) - mu1 * mu1 + 1e-5f);

    unsigned orig0[8], orig1[8], it0[8], it1[8];
#pragma unroll
    for (int s = 0; s < 8; s++) {
        float z0 = (e0[s] - mu0) * rstd0 * gv[s] + bv[s];
        float z1 = (e1[s] - mu1) * rstd1 * gv[s] + bv[s];
        unsigned u0 = __float_as_uint(z0);
        unsigned u1 = __float_as_uint(z1);
        orig0[s] = (u0 & 0x80000000u) ? ~u0 : (u0 | 0x80000000u);
        orig1[s] = (u1 & 0x80000000u) ? ~u1 : (u1 | 0x80000000u);
        it0[s] = orig0[s];
        it1[s] = orig1[s];
    }

    bitonic256_x2(it0, it1, lane);

    unsigned* sb0 = sortbuf[warp * 2];
    unsigned* sb1 = sortbuf[warp * 2 + 1];
#pragma unroll
    for (int s = 0; s < 8; s++) {
        sb0[SKW(lane * 8 + s)] = it0[s];
        sb1[SKW(lane * 8 + s)] = it1[s];
    }
    __syncwarp();

    unsigned lo0[8], lo1[8];
#pragma unroll
    for (int s = 0; s < 8; s++) { lo0[s] = 0; lo1[s] = 0; }
#pragma unroll
    for (int wstep = 128; wstep > 0; wstep >>= 1) {
#pragma unroll
        for (int s = 0; s < 8; s++) {
            if (sb0[SKW(lo0[s] + wstep - 1)] < orig0[s]) lo0[s] += wstep;
            if (sb1[SKW(lo1[s] + wstep - 1)] < orig1[s]) lo1[s] += wstep;
        }
    }
    __syncwarp();

    __nv_bfloat16* st0 = (__nv_bfloat16*)sb0;
    __nv_bfloat16* st1 = (__nv_bfloat16*)sb1;
#pragma unroll
    for (int s = 0; s < 8; s++) {
        st0[s * 32 + lane] = __float2bfloat16((float)(2 * (int)lo0[s] - 255));
        st1[s * 32 + lane] = __float2bfloat16((float)(2 * (int)lo1[s] - 255));
    }
    __syncwarp();

    size_t base = (size_t)row0 * D_DIM;
    *(uint4*)(g_c2 + base + lane * 8) = ((const uint4*)st0)[lane];
    *(uint4*)(g_c2 + base + D_DIM + lane * 8) = ((const uint4*)st1)[lane];
}

// ---------------------------------------------------------------------------
// Shared bf16 HMMA mainloop (2 CTAs/SM, double-buffered K=64 chunks,
// pitch 72). acc[4][4][4] f32, exact. Ends WITHOUT trailing sync.
// ---------------------------------------------------------------------------
#define LDB 72    // chunk pitch in bf16 (144B rows: LDSM + cp.async CF)
#define TSP 132   // transpose staging pitch (floats)
#define SMEM_K2 73728
#define SMEM_K2B 77824              // + 4KB param region (sst) past tiles
#define ADJ_SCALE (0.25f / (1398080.0f + 1e-8f))

__constant__ int IT_MAP[36] = {0,0,0,0,0,0,0,0, 1,1,1,1,1,1,1, 2,2,2,2,2,2,
                               3,3,3,3,3, 4,4,4,4, 5,5,5, 6,6, 7};
__constant__ int JT_MAP[36] = {0,1,2,3,4,5,6,7, 1,2,3,4,5,6,7, 2,3,4,5,6,7,
                               3,4,5,6,7, 4,5,6,7, 5,6,7, 6,7, 7};

__device__ __forceinline__ unsigned sptr(const void* p) {
    return (unsigned)__cvta_generic_to_shared(p);
}
__device__ __forceinline__ void cpasync16(unsigned dst, const void* src) {
    asm volatile("cp.async.cg.shared.global [%0], [%1], 16;\n"
                 :: "r"(dst), "l"(src));
}
__device__ __forceinline__ void cpcommit() {
    asm volatile("cp.async.commit_group;\n");
}
template <int N>
__device__ __forceinline__ void cpwait() {
    asm volatile("cp.async.wait_group %0;\n" :: "n"(N));
}
__device__ __forceinline__ void ldm4(unsigned& r0, unsigned& r1, unsigned& r2,
                                     unsigned& r3, unsigned a) {
    asm volatile("ldmatrix.sync.aligned.m8n8.x4.shared.b16 {%0,%1,%2,%3}, [%4];\n"
                 : "=r"(r0), "=r"(r1), "=r"(r2), "=r"(r3) : "r"(a));
}
__device__ __forceinline__ void mma16816(float* d, const unsigned* a,
                                         unsigned b0, unsigned b1) {
    asm volatile(
        "mma.sync.aligned.m16n8k16.row.col.f32.bf16.bf16.f32 "
        "{%0,%1,%2,%3},{%4,%5,%6,%7},{%8,%9},{%0,%1,%2,%3};\n"
        : "+f"(d[0]), "+f"(d[1]), "+f"(d[2]), "+f"(d[3])
        : "r"(a[0]), "r"(a[1]), "r"(a[2]), "r"(a[3]), "r"(b0), "r"(b1));
}

__device__ __forceinline__ void k2_mainloop(
    int b, int it, int jt, bool diag, __nv_bfloat16* smem, float acc[4][4][4])
{
    __nv_bfloat16* Ast[2] = { smem, smem + 128 * LDB };
    __nv_bfloat16* Bst[2] = { diag ? Ast[0] : smem + 2 * 128 * LDB,
                              diag ? Ast[1] : smem + 3 * 128 * LDB };

    const __nv_bfloat16* Ag = g_c2 + ((size_t)b * N_DIM + it * 128) * D_DIM;
    const __nv_bfloat16* Bg = g_c2 + ((size_t)b * N_DIM + jt * 128) * D_DIM;

    int tid = threadIdx.x;

#define LOAD_CHUNK(c, Ad, Bd)                                                  \
    do {                                                                       \
        _Pragma("unroll")                                                      \
        for (int i = 0; i < 4; i++) {                                          \
            int idx = tid + i * 256;                                           \
            int r = idx >> 3, line = idx & 7;                                  \
            int off = (c) * 64 + line * 8;                                     \
            cpasync16(sptr((Ad) + r * LDB + line * 8), Ag + r * D_DIM + off);  \
        }                                                                      \
        if (!diag) {                                                           \
            _Pragma("unroll")                                                  \
            for (int i = 0; i < 4; i++) {                                      \
                int idx = tid + i * 256;                                       \
                int r = idx >> 3, line = idx & 7;                              \
                int off = (c) * 64 + line * 8;                                 \
                cpasync16(sptr((Bd) + r * LDB + line * 8), Bg + r * D_DIM + off); \
            }                                                                  \
        }                                                                      \
        cpcommit();                                                            \
    } while (0)

    LOAD_CHUNK(0, Ast[0], Bst[0]);
    LOAD_CHUNK(1, Ast[1], Bst[1]);

    int wid = tid >> 5, lane = tid & 31;
    int wm = (wid >> 2) * 64, wn = (wid & 3) * 32;

#pragma unroll
    for (int mf = 0; mf < 4; mf++)
#pragma unroll
        for (int nf = 0; nf < 4; nf++)
#pragma unroll
            for (int r = 0; r < 4; r++) acc[mf][nf][r] = 0.f;

#pragma unroll
    for (int c = 0; c < 4; c++) {
        if (c < 3) cpwait<1>(); else cpwait<0>();
        __syncthreads();
        __nv_bfloat16* Asb = Ast[c & 1];
        __nv_bfloat16* Bsb = Bst[c & 1];
        unsigned aaddr[4];
#pragma unroll
        for (int mf = 0; mf < 4; mf++)
            aaddr[mf] = sptr(Asb + (wm + mf * 16 + (lane & 15)) * LDB
                             + ((lane >> 4) << 3));
        unsigned baddr = sptr(Bsb + (wn + lane) * LDB);

#pragma unroll
        for (int kk = 0; kk < 64; kk += 16) {
            unsigned a[4][4];
#pragma unroll
            for (int mf = 0; mf < 4; mf++)
                ldm4(a[mf][0], a[mf][1], a[mf][2], a[mf][3], aaddr[mf] + 2 * kk);
            unsigned bl[4], bh[4];
            ldm4(bl[0], bl[1], bl[2], bl[3], baddr + 2 * kk);
            ldm4(bh[0], bh[1], bh[2], bh[3], baddr + 2 * kk + 16);
#pragma unroll
            for (int mf = 0; mf < 4; mf++)
#pragma unroll
                for (int nf = 0; nf < 4; nf++)
                    mma16816(acc[mf][nf], a[mf], bl[nf], bh[nf]);
        }
        if (c + 2 < 4) {
            __syncthreads();
            LOAD_CHUNK(c + 2, Asb, Bsb);
        }
    }
#undef LOAD_CHUNK
}

__device__ __forceinline__ float adjv(float a) {
    return fabsf(a) * ADJ_SCALE;
}

// ---------------------------------------------------------------------------
// K2a: mainloop + per-tile row/col (sum, sumsq) LN partials. No adj write.
// ---------------------------------------------------------------------------
__global__ __launch_bounds__(256, 2) void k2a_stats()
{
    extern __shared__ __nv_bfloat16 smem[];
    int b = blockIdx.z, tt = blockIdx.x;
    int it = IT_MAP[tt], jt = JT_MAP[tt];
    bool diag = (it == jt);

    float acc[4][4][4];
    k2_mainloop(b, it, jt, diag, smem, acc);
    __syncthreads();    // all warps done with tiles; smem reusable

    int tid = threadIdx.x, wid = tid >> 5, lane = tid & 31;
    int wm = (wid >> 2) * 64, wn = (wid & 3) * 32;
    float* sred = (float*)smem;                 // [128][4 wn-groups][2]

    // ---- row partials ----
    float rs[8], rq[8];
#pragma unroll
    for (int mf = 0; mf < 4; mf++) {
        float a0 = 0.f, c0 = 0.f, a1 = 0.f, c1 = 0.f;
#pragma unroll
        for (int nf = 0; nf < 4; nf++) {
            float v0 = adjv(acc[mf][nf][0]), v1 = adjv(acc[mf][nf][1]);
            float v2 = adjv(acc[mf][nf][2]), v3 = adjv(acc[mf][nf][3]);
            a0 += v0 + v1; c0 += v0 * v0 + v1 * v1;
            a1 += v2 + v3; c1 += v2 * v2 + v3 * v3;
        }
        rs[mf * 2] = a0; rq[mf * 2] = c0;
        rs[mf * 2 + 1] = a1; rq[mf * 2 + 1] = c1;
    }
#pragma unroll
    for (int o = 1; o <= 2; o <<= 1)
#pragma unroll
        for (int m = 0; m < 8; m++) {
            rs[m] += __shfl_xor_sync(0xffffffffu, rs[m], o);
            rq[m] += __shfl_xor_sync(0xffffffffu, rq[m], o);
        }
    if ((lane & 3) == 0) {
#pragma unroll
        for (int m = 0; m < 8; m++) {
            int r = wm + (m >> 1) * 16 + (m & 1) * 8 + (lane >> 2);
            sred[(r * 4 + (wid & 3)) * 2]     = rs[m];
            sred[(r * 4 + (wid & 3)) * 2 + 1] = rq[m];
        }
    }
    __syncthreads();
    if (tid < 128) {
        float S = 0.f, Q = 0.f;
#pragma unroll
        for (int g = 0; g < 4; g++) {
            S += sred[(tid * 4 + g) * 2];
            Q += sred[(tid * 4 + g) * 2 + 1];
        }
        float2 v; v.x = S; v.y = Q;
        *(float2*)(g_part + (((size_t)b * 8 + it) * 8 + jt) * 256 + tid * 2) = v;
    }
    if (diag) return;
    __syncthreads();

    // ---- col partials ----
    float* scol = sred;
    float cs[8], cq[8];
#pragma unroll
    for (int nf = 0; nf < 4; nf++) {
        float a0 = 0.f, c0 = 0.f, a1 = 0.f, c1 = 0.f;
#pragma unroll
        for (int mf = 0; mf < 4; mf++) {
            float v0 = adjv(acc[mf][nf][0]), v1 = adjv(acc[mf][nf][1]);
            float v2 = adjv(acc[mf][nf][2]), v3 = adjv(acc[mf][nf][3]);
            a0 += v0 + v2; c0 += v0 * v0 + v2 * v2;
            a1 += v1 + v3; c1 += v1 * v1 + v3 * v3;
        }
        cs[nf * 2] = a0; cq[nf * 2] = c0;
        cs[nf * 2 + 1] = a1; cq[nf * 2 + 1] = c1;
    }
#pragma unroll
    for (int o = 4; o <= 16; o <<= 1)
#pragma unroll
        for (int n = 0; n < 8; n++) {
            cs[n] += __shfl_xor_sync(0xffffffffu, cs[n], o);
            cq[n] += __shfl_xor_sync(0xffffffffu, cq[n], o);
        }
    if (lane < 4) {
#pragma unroll
        for (int n = 0; n < 8; n++) {
            int c = wn + lane * 2 + (n >> 1) * 8 + (n & 1);
            scol[(c * 2 + (wid >> 2)) * 2]     = cs[n];
            scol[(c * 2 + (wid >> 2)) * 2 + 1] = cq[n];
        }
    }
    __syncthreads();
    if (tid < 128) {
        float S = scol[(tid * 2) * 2]     + scol[(tid * 2 + 1) * 2];
        float Q = scol[(tid * 2) * 2 + 1] + scol[(tid * 2 + 1) * 2 + 1];
        float2 v; v.x = S; v.y = Q;
        *(float2*)(g_part + (((size_t)b * 8 + jt) * 8 + it) * 256 + tid * 2) = v;
    }
}

// ---------------------------------------------------------------------------
// K_stats: finalize mu/rstd per output row from the 8 partial slots.
// ---------------------------------------------------------------------------
__global__ void k_stats()
{
    int row = blockIdx.x * 256 + threadIdx.x;
    int blk = row >> 7, rowin = row & 127;
    const float* p = g_part + (size_t)blk * 8 * 256 + rowin * 2;
    float S = 0.f, Q = 0.f;
#pragma unroll
    for (int s = 0; s < 8; s++) { S += p[s * 256]; Q += p[s * 256 + 1]; }
    float mu = S * (1.0f / N_DIM);
    float var = Q * (1.0f / N_DIM) - mu * mu;
    g_mu[row] = mu;
    g_rstd[row] = rsqrtf(var + 1e-5f);
}

// ---------------------------------------------------------------------------
// K2b: identical mainloop (same f32 S) + fused LN + ReLU + single write.
// LN params preloaded before the mainloop (sst past the tile buffers).
// ---------------------------------------------------------------------------
__global__ __launch_bounds__(256, 2) void k2b_write(
    float* __restrict__ out, const float* __restrict__ sg,
    const float* __restrict__ sb)
{
    extern __shared__ __nv_bfloat16 smem[];
    int b = blockIdx.z, tt = blockIdx.x;
    int it = IT_MAP[tt], jt = JT_MAP[tt];
    bool diag = (it == jt);
    int tid = threadIdx.x;

    float* sst = (float*)((char*)smem + SMEM_K2);      // 1024 floats
    if (tid < 128) {
        int iG = it * 128 + tid, jG = jt * 128 + tid;
        int base = b * N_DIM;
        sst[0 * 128 + tid] = g_mu[base + iG];
        sst[1 * 128 + tid] = g_rstd[base + iG];
        sst[2 * 128 + tid] = sg[jG];
        sst[3 * 128 + tid] = sb[jG];
        sst[4 * 128 + tid] = g_mu[base + jG];
        sst[5 * 128 + tid] = g_rstd[base + jG];
        sst[6 * 128 + tid] = sg[iG];
        sst[7 * 128 + tid] = sb[iG];
    }

    float acc[4][4][4];
    k2_mainloop(b, it, jt, diag, smem, acc);
    __syncthreads();    // tiles done; sst visible; ts region reusable

    int wid = tid >> 5, lane = tid & 31;
    int wm = (wid >> 2) * 64, wn = (wid & 3) * 32;
    int il = wm + (lane >> 2), jl = wn + (lane & 3) * 2;

    float* ts = (float*)smem;                          // [128][TSP] staging
    float* ob = out + (size_t)b * N_DIM * N_DIM;

    // direct tile: rows i (stats), cols j (affine)
#pragma unroll
    for (int mf = 0; mf < 4; mf++) {
        int i0 = il + mf * 16;
        float mA = sst[i0], rA = sst[128 + i0];
        float mB = sst[i0 + 8], rB = sst[128 + i0 + 8];
#pragma unroll
        for (int nf = 0; nf < 4; nf++) {
            int j0 = jl + nf * 8;
            float gj0 = sst[256 + j0], bj0 = sst[384 + j0];
            float gj1 = sst[256 + j0 + 1], bj1 = sst[384 + j0 + 1];
            float2 v0, v1;
            v0.x = fmaxf((adjv(acc[mf][nf][0]) - mA) * rA * gj0 + bj0, 0.f);
            v0.y = fmaxf((adjv(acc[mf][nf][1]) - mA) * rA * gj1 + bj1, 0.f);
            v1.x = fmaxf((adjv(acc[mf][nf][2]) - mB) * rB * gj0 + bj0, 0.f);
            v1.y = fmaxf((adjv(acc[mf][nf][3]) - mB) * rB * gj1 + bj1, 0.f);
            size_t iG0 = (size_t)(it * 128 + i0) * N_DIM + jt * 128 + j0;
            *(float2*)(ob + iG0) = v0;
            *(float2*)(ob + iG0 + 8 * N_DIM) = v1;
        }
    }

    if (diag) return;

    // mirror tile: rows j (stats), cols i (affine); normalize, stage, write
#pragma unroll
    for (int mf = 0; mf < 4; mf++) {
        int i0 = il + mf * 16;
        float gi0 = sst[768 + i0], bi0 = sst[896 + i0];
        float gi8 = sst[768 + i0 + 8], bi8 = sst[896 + i0 + 8];
#pragma unroll
        for (int nf = 0; nf < 4; nf++) {
            int j0 = jl + nf * 8;
            float mJ0 = sst[512 + j0], rJ0 = sst[640 + j0];
            float mJ1 = sst[512 + j0 + 1], rJ1 = sst[640 + j0 + 1];
            ts[(j0    ) * TSP + i0    ] =
                fmaxf((adjv(acc[mf][nf][0]) - mJ0) * rJ0 * gi0 + bi0, 0.f);
            ts[(j0 + 1) * TSP + i0    ] =
                fmaxf((adjv(acc[mf][nf][1]) - mJ1) * rJ1 * gi0 + bi0, 0.f);
            ts[(j0    ) * TSP + i0 + 8] =
                fmaxf((adjv(acc[mf][nf][2]) - mJ0) * rJ0 * gi8 + bi8, 0.f);
            ts[(j0 + 1) * TSP + i0 + 8] =
                fmaxf((adjv(acc[mf][nf][3]) - mJ1) * rJ1 * gi8 + bi8, 0.f);
        }
    }
    __syncthreads();

#pragma unroll
    for (int pass = 0; pass < 16; pass++) {
        int r = (tid >> 5) + pass * 8;
        int c4 = (tid & 31) * 4;
        float4 v = *(float4*)&ts[r * TSP + c4];
        *(float4*)(ob + (size_t)(jt * 128 + r) * N_DIM + it * 128 + c4) = v;
    }
}

// ---------------------------------------------------------------------------
extern "C" void kernel_launch(void* const* d_in, const int* in_sizes, int n_in,
                              void* d_out, int out_size)
{
    (void)in_sizes; (void)n_in; (void)out_size;
    const float* x        = (const float*)d_in[0];
    const float* conv_w   = (const float*)d_in[1];
    const float* conv_b   = (const float*)d_in[2];
    const float* time_g   = (const float*)d_in[3];
    const float* time_b   = (const float*)d_in[4];
    const float* static_g = (const float*)d_in[5];
    const float* static_b = (const float*)d_in[6];
    float* out = (float*)d_out;

    cudaFuncSetAttribute(k2a_stats, cudaFuncAttributeMaxDynamicSharedMemorySize,
                         SMEM_K2);
    cudaFuncSetAttribute(k2b_write, cudaFuncAttributeMaxDynamicSharedMemorySize,
                         SMEM_K2B);

    k1_rank<<<NROWS / 16, 256>>>(x, conv_w, conv_b, time_g, time_b);

    dim3 g2(36, 1, 64);
    k2a_stats<<<g2, 256, SMEM_K2>>>();
    k_stats<<<NROWS / 256, 256>>>();
    k2b_write<<<g2, 256, SMEM_K2B>>>(out, static_g, static_b);
}

// round 17
// speedup vs baseline: 1.0369x; 1.0072x over previous
#include <cuda_runtime.h>
#include <cuda_bf16.h>
#include <cstdint>
#include <cstddef>

#define B_DIM 64
#define N_DIM 1024
#define D_DIM 256
#define T_DIM 13
#define C_DIM 2
#define KX (C_DIM * T_DIM)          // 26
#define NROWS (B_DIM * N_DIM)        // 65536

// c2 = 2*rank - 255 per (row, d), exact in bf16. 32 MB static scratch.
__device__ __nv_bfloat16 g_c2[(size_t)NROWS * D_DIM];
// per-tile LN partials: [b][rowblock][slot][128 rows][{sum,sq}]  (4 MB)
__device__ float g_part[(size_t)B_DIM * 8 * 8 * 256];
__device__ float g_mu[NROWS];
__device__ float g_rstd[NROWS];

#define SKW(i) ((i) + ((i) >> 5))
#define SBUF_LEN 264

// ---------------------------------------------------------------------------
// Dual bitonic sort of two 256-key sets (2x ILP). 8 keys/lane, p = lane*8+s.
// ---------------------------------------------------------------------------
__device__ __forceinline__ void bitonic256_x2(unsigned a0[8], unsigned a1[8],
                                              int lane)
{
#pragma unroll
    for (int ks = 1; ks <= 8; ks++) {
        const int k = 1 << ks;
#pragma unroll
        for (int js = ks - 1; js >= 0; js--) {
            const int j = 1 << js;
            if (j >= 8) {
                const int jl = j >> 3;
                bool up = ((lane & (k >> 3)) == 0);
                bool keepmin = (((lane & jl) == 0) == up);
#pragma unroll
                for (int s = 0; s < 8; s++) {
                    unsigned o0 = __shfl_xor_sync(0xffffffffu, a0[s], jl);
                    unsigned o1 = __shfl_xor_sync(0xffffffffu, a1[s], jl);
                    unsigned mn0 = a0[s] < o0 ? a0[s] : o0;
                    unsigned mx0 = a0[s] < o0 ? o0 : a0[s];
                    unsigned mn1 = a1[s] < o1 ? a1[s] : o1;
                    unsigned mx1 = a1[s] < o1 ? o1 : a1[s];
                    a0[s] = keepmin ? mn0 : mx0;
                    a1[s] = keepmin ? mn1 : mx1;
                }
            } else {
#pragma unroll
                for (int s = 0; s < 8; s++) {
                    if ((s & j) == 0) {
                        int a = s, b2 = s | j;
                        int p = (lane << 3) | a;
                        bool up = ((p & k) == 0);
                        unsigned x0 = a0[a], y0 = a0[b2];
                        unsigned x1 = a1[a], y1 = a1[b2];
                        unsigned mn0 = x0 < y0 ? x0 : y0;
                        unsigned mx0 = x0 < y0 ? y0 : x0;
                        unsigned mn1 = x1 < y1 ? x1 : y1;
                        unsigned mx1 = x1 < y1 ? y1 : x1;
                        a0[a]  = up ? mn0 : mx0;
                        a0[b2] = up ? mx0 : mn0;
                        a1[a]  = up ? mn1 : mx1;
                        a1[b2] = up ? mx1 : mn1;
                    }
                }
            }
        }
    }
}

// ---------------------------------------------------------------------------
// K1: conv + LayerNorm(D) + rank (dual bitonic + skewed binary search),
// 2 rows/warp. Output bf16 c2 = 2*rank - 255.
// ---------------------------------------------------------------------------
__global__ __launch_bounds__(256) void k1_rank(
    const float* __restrict__ x, const float* __restrict__ w,
    const float* __restrict__ cb, const float* __restrict__ tg,
    const float* __restrict__ tb)
{
    __shared__ float wst[KX * D_DIM];
    __shared__ float scb[D_DIM];
    __shared__ float sxs[16][KX + 2];
    __shared__ unsigned sortbuf[16][SBUF_LEN];

    int tid = threadIdx.x;
#pragma unroll
    for (int k = 0; k < KX; k++) wst[k * D_DIM + tid] = w[tid * KX + k];
    scb[tid] = cb[tid];

    int warp = tid >> 5, lane = tid & 31;
    int row0 = blockIdx.x * 16 + warp * 2;

#pragma unroll
    for (int r = 0; r < 2; r++) {
        int row = row0 + r;
        int b = row >> 10, n = row & 1023;
        if (lane < KX) {
            int c = lane / T_DIM, t = lane - c * T_DIM;
            sxs[warp * 2 + r][lane] =
                x[(((size_t)b * C_DIM + c) * N_DIM + n) * T_DIM + t];
        }
    }
    __syncthreads();

    float gv[8], bv[8];
#pragma unroll
    for (int s = 0; s < 8; s++) { gv[s] = tg[s * 32 + lane]; bv[s] = tb[s * 32 + lane]; }

    float e0[8], e1[8];
#pragma unroll
    for (int s = 0; s < 8; s++) { e0[s] = scb[s * 32 + lane]; e1[s] = e0[s]; }
#pragma unroll
    for (int k = 0; k < KX; k++) {
        float x0 = sxs[warp * 2][k], x1 = sxs[warp * 2 + 1][k];
#pragma unroll
        for (int s = 0; s < 8; s++) {
            float wv = wst[k * D_DIM + s * 32 + lane];
            e0[s] += x0 * wv;
            e1[s] += x1 * wv;
        }
    }

    float s0 = 0.f, q0 = 0.f, s1 = 0.f, q1 = 0.f;
#pragma unroll
    for (int s = 0; s < 8; s++) {
        s0 += e0[s]; q0 += e0[s] * e0[s];
        s1 += e1[s]; q1 += e1[s] * e1[s];
    }
#pragma unroll
    for (int o = 16; o > 0; o >>= 1) {
        s0 += __shfl_xor_sync(0xffffffffu, s0, o);
        q0 += __shfl_xor_sync(0xffffffffu, q0, o);
        s1 += __shfl_xor_sync(0xffffffffu, s1, o);
        q1 += __shfl_xor_sync(0xffffffffu, q1, o);
    }
    float mu0 = s0 * (1.0f / D_DIM);
    float rstd0 = rsqrtf(q0 * (1.0f / D_DIM) - mu0 * mu0 + 1e-5f);
    float mu1 = s1 * (1.0f / D_DIM);
    float rstd1 = rsqrtf(q1 * (1.0f / D_DIM) - mu1 * mu1 + 1e-5f);

    unsigned orig0[8], orig1[8], it0[8], it1[8];
#pragma unroll
    for (int s = 0; s < 8; s++) {
        float z0 = (e0[s] - mu0) * rstd0 * gv[s] + bv[s];
        float z1 = (e1[s] - mu1) * rstd1 * gv[s] + bv[s];
        unsigned u0 = __float_as_uint(z0);
        unsigned u1 = __float_as_uint(z1);
        orig0[s] = (u0 & 0x80000000u) ? ~u0 : (u0 | 0x80000000u);
        orig1[s] = (u1 & 0x80000000u) ? ~u1 : (u1 | 0x80000000u);
        it0[s] = orig0[s];
        it1[s] = orig1[s];
    }

    bitonic256_x2(it0, it1, lane);

    unsigned* sb0 = sortbuf[warp * 2];
    unsigned* sb1 = sortbuf[warp * 2 + 1];
#pragma unroll
    for (int s = 0; s < 8; s++) {
        sb0[SKW(lane * 8 + s)] = it0[s];
        sb1[SKW(lane * 8 + s)] = it1[s];
    }
    __syncwarp();

    unsigned lo0[8], lo1[8];
#pragma unroll
    for (int s = 0; s < 8; s++) { lo0[s] = 0; lo1[s] = 0; }
#pragma unroll
    for (int wstep = 128; wstep > 0; wstep >>= 1) {
#pragma unroll
        for (int s = 0; s < 8; s++) {
            if (sb0[SKW(lo0[s] + wstep - 1)] < orig0[s]) lo0[s] += wstep;
            if (sb1[SKW(lo1[s] + wstep - 1)] < orig1[s]) lo1[s] += wstep;
        }
    }
    __syncwarp();

    __nv_bfloat16* st0 = (__nv_bfloat16*)sb0;
    __nv_bfloat16* st1 = (__nv_bfloat16*)sb1;
#pragma unroll
    for (int s = 0; s < 8; s++) {
        st0[s * 32 + lane] = __float2bfloat16((float)(2 * (int)lo0[s] - 255));
        st1[s * 32 + lane] = __float2bfloat16((float)(2 * (int)lo1[s] - 255));
    }
    __syncwarp();

    size_t base = (size_t)row0 * D_DIM;
    *(uint4*)(g_c2 + base + lane * 8) = ((const uint4*)st0)[lane];
    *(uint4*)(g_c2 + base + D_DIM + lane * 8) = ((const uint4*)st1)[lane];
}

// ---------------------------------------------------------------------------
// Shared bf16 HMMA mainloop (2 CTAs/SM, double-buffered K=64 chunks,
// pitch 72). acc[4][4][4] f32, exact. Ends WITHOUT trailing sync.
// ---------------------------------------------------------------------------
#define LDB 72    // chunk pitch in bf16 (144B rows: LDSM + cp.async CF)
#define TSP 132   // transpose staging pitch (floats)
#define SMEM_K2 73728
#define SMEM_K2B 77824              // + 4KB param region (sst) past tiles
#define ADJ_SCALE (0.25f / (1398080.0f + 1e-8f))

__constant__ int IT_MAP[36] = {0,0,0,0,0,0,0,0, 1,1,1,1,1,1,1, 2,2,2,2,2,2,
                               3,3,3,3,3, 4,4,4,4, 5,5,5, 6,6, 7};
__constant__ int JT_MAP[36] = {0,1,2,3,4,5,6,7, 1,2,3,4,5,6,7, 2,3,4,5,6,7,
                               3,4,5,6,7, 4,5,6,7, 5,6,7, 6,7, 7};

__device__ __forceinline__ unsigned sptr(const void* p) {
    return (unsigned)__cvta_generic_to_shared(p);
}
__device__ __forceinline__ void cpasync16(unsigned dst, const void* src) {
    asm volatile("cp.async.cg.shared.global [%0], [%1], 16;\n"
                 :: "r"(dst), "l"(src));
}
__device__ __forceinline__ void cpcommit() {
    asm volatile("cp.async.commit_group;\n");
}
template <int N>
__device__ __forceinline__ void cpwait() {
    asm volatile("cp.async.wait_group %0;\n" :: "n"(N));
}
__device__ __forceinline__ void ldm4(unsigned& r0, unsigned& r1, unsigned& r2,
                                     unsigned& r3, unsigned a) {
    asm volatile("ldmatrix.sync.aligned.m8n8.x4.shared.b16 {%0,%1,%2,%3}, [%4];\n"
                 : "=r"(r0), "=r"(r1), "=r"(r2), "=r"(r3) : "r"(a));
}
__device__ __forceinline__ void mma16816(float* d, const unsigned* a,
                                         unsigned b0, unsigned b1) {
    asm volatile(
        "mma.sync.aligned.m16n8k16.row.col.f32.bf16.bf16.f32 "
        "{%0,%1,%2,%3},{%4,%5,%6,%7},{%8,%9},{%0,%1,%2,%3};\n"
        : "+f"(d[0]), "+f"(d[1]), "+f"(d[2]), "+f"(d[3])
        : "r"(a[0]), "r"(a[1]), "r"(a[2]), "r"(a[3]), "r"(b0), "r"(b1));
}
// streaming (evict-first) stores: output is write-once, keep c2 in L2
__device__ __forceinline__ void stcs2(float* p, float2 v) {
    asm volatile("st.global.cs.v2.f32 [%0], {%1, %2};\n"
                 :: "l"(p), "f"(v.x), "f"(v.y) : "memory");
}
__device__ __forceinline__ void stcs4(float* p, float4 v) {
    asm volatile("st.global.cs.v4.f32 [%0], {%1, %2, %3, %4};\n"
                 :: "l"(p), "f"(v.x), "f"(v.y), "f"(v.z), "f"(v.w) : "memory");
}

__device__ __forceinline__ void k2_mainloop(
    int b, int it, int jt, bool diag, __nv_bfloat16* smem, float acc[4][4][4])
{
    __nv_bfloat16* Ast[2] = { smem, smem + 128 * LDB };
    __nv_bfloat16* Bst[2] = { diag ? Ast[0] : smem + 2 * 128 * LDB,
                              diag ? Ast[1] : smem + 3 * 128 * LDB };

    const __nv_bfloat16* Ag = g_c2 + ((size_t)b * N_DIM + it * 128) * D_DIM;
    const __nv_bfloat16* Bg = g_c2 + ((size_t)b * N_DIM + jt * 128) * D_DIM;

    int tid = threadIdx.x;

#define LOAD_CHUNK(c, Ad, Bd)                                                  \
    do {                                                                       \
        _Pragma("unroll")                                                      \
        for (int i = 0; i < 4; i++) {                                          \
            int idx = tid + i * 256;                                           \
            int r = idx >> 3, line = idx & 7;                                  \
            int off = (c) * 64 + line * 8;                                     \
            cpasync16(sptr((Ad) + r * LDB + line * 8), Ag + r * D_DIM + off);  \
        }                                                                      \
        if (!diag) {                                                           \
            _Pragma("unroll")                                                  \
            for (int i = 0; i < 4; i++) {                                      \
                int idx = tid + i * 256;                                       \
                int r = idx >> 3, line = idx & 7;                              \
                int off = (c) * 64 + line * 8;                                 \
                cpasync16(sptr((Bd) + r * LDB + line * 8), Bg + r * D_DIM + off); \
            }                                                                  \
        }                                                                      \
        cpcommit();                                                            \
    } while (0)

    LOAD_CHUNK(0, Ast[0], Bst[0]);
    LOAD_CHUNK(1, Ast[1], Bst[1]);

    int wid = tid >> 5, lane = tid & 31;
    int wm = (wid >> 2) * 64, wn = (wid & 3) * 32;

#pragma unroll
    for (int mf = 0; mf < 4; mf++)
#pragma unroll
        for (int nf = 0; nf < 4; nf++)
#pragma unroll
            for (int r = 0; r < 4; r++) acc[mf][nf][r] = 0.f;

#pragma unroll
    for (int c = 0; c < 4; c++) {
        if (c < 3) cpwait<1>(); else cpwait<0>();
        __syncthreads();
        __nv_bfloat16* Asb = Ast[c & 1];
        __nv_bfloat16* Bsb = Bst[c & 1];
        unsigned aaddr[4];
#pragma unroll
        for (int mf = 0; mf < 4; mf++)
            aaddr[mf] = sptr(Asb + (wm + mf * 16 + (lane & 15)) * LDB
                             + ((lane >> 4) << 3));
        unsigned baddr = sptr(Bsb + (wn + lane) * LDB);

#pragma unroll
        for (int kk = 0; kk < 64; kk += 16) {
            unsigned a[4][4];
#pragma unroll
            for (int mf = 0; mf < 4; mf++)
                ldm4(a[mf][0], a[mf][1], a[mf][2], a[mf][3], aaddr[mf] + 2 * kk);
            unsigned bl[4], bh[4];
            ldm4(bl[0], bl[1], bl[2], bl[3], baddr + 2 * kk);
            ldm4(bh[0], bh[1], bh[2], bh[3], baddr + 2 * kk + 16);
#pragma unroll
            for (int mf = 0; mf < 4; mf++)
#pragma unroll
                for (int nf = 0; nf < 4; nf++)
                    mma16816(acc[mf][nf], a[mf], bl[nf], bh[nf]);
        }
        if (c + 2 < 4) {
            __syncthreads();
            LOAD_CHUNK(c + 2, Asb, Bsb);
        }
    }
#undef LOAD_CHUNK
}

__device__ __forceinline__ float adjv(float a) {
    return fabsf(a) * ADJ_SCALE;
}

// ---------------------------------------------------------------------------
// K2a: mainloop + per-tile row/col (sum, sumsq) LN partials. No adj write.
// ---------------------------------------------------------------------------
__global__ __launch_bounds__(256, 2) void k2a_stats()
{
    extern __shared__ __nv_bfloat16 smem[];
    int b = blockIdx.z, tt = blockIdx.x;
    int it = IT_MAP[tt], jt = JT_MAP[tt];
    bool diag = (it == jt);

    float acc[4][4][4];
    k2_mainloop(b, it, jt, diag, smem, acc);
    __syncthreads();    // all warps done with tiles; smem reusable

    int tid = threadIdx.x, wid = tid >> 5, lane = tid & 31;
    int wm = (wid >> 2) * 64, wn = (wid & 3) * 32;
    float* sred = (float*)smem;                 // [128][4 wn-groups][2]

    // ---- row partials ----
    float rs[8], rq[8];
#pragma unroll
    for (int mf = 0; mf < 4; mf++) {
        float a0 = 0.f, c0 = 0.f, a1 = 0.f, c1 = 0.f;
#pragma unroll
        for (int nf = 0; nf < 4; nf++) {
            float v0 = adjv(acc[mf][nf][0]), v1 = adjv(acc[mf][nf][1]);
            float v2 = adjv(acc[mf][nf][2]), v3 = adjv(acc[mf][nf][3]);
            a0 += v0 + v1; c0 += v0 * v0 + v1 * v1;
            a1 += v2 + v3; c1 += v2 * v2 + v3 * v3;
        }
        rs[mf * 2] = a0; rq[mf * 2] = c0;
        rs[mf * 2 + 1] = a1; rq[mf * 2 + 1] = c1;
    }
#pragma unroll
    for (int o = 1; o <= 2; o <<= 1)
#pragma unroll
        for (int m = 0; m < 8; m++) {
            rs[m] += __shfl_xor_sync(0xffffffffu, rs[m], o);
            rq[m] += __shfl_xor_sync(0xffffffffu, rq[m], o);
        }
    if ((lane & 3) == 0) {
#pragma unroll
        for (int m = 0; m < 8; m++) {
            int r = wm + (m >> 1) * 16 + (m & 1) * 8 + (lane >> 2);
            sred[(r * 4 + (wid & 3)) * 2]     = rs[m];
            sred[(r * 4 + (wid & 3)) * 2 + 1] = rq[m];
        }
    }
    __syncthreads();
    if (tid < 128) {
        float S = 0.f, Q = 0.f;
#pragma unroll
        for (int g = 0; g < 4; g++) {
            S += sred[(tid * 4 + g) * 2];
            Q += sred[(tid * 4 + g) * 2 + 1];
        }
        float2 v; v.x = S; v.y = Q;
        *(float2*)(g_part + (((size_t)b * 8 + it) * 8 + jt) * 256 + tid * 2) = v;
    }
    if (diag) return;
    __syncthreads();

    // ---- col partials ----
    float* scol = sred;
    float cs[8], cq[8];
#pragma unroll
    for (int nf = 0; nf < 4; nf++) {
        float a0 = 0.f, c0 = 0.f, a1 = 0.f, c1 = 0.f;
#pragma unroll
        for (int mf = 0; mf < 4; mf++) {
            float v0 = adjv(acc[mf][nf][0]), v1 = adjv(acc[mf][nf][1]);
            float v2 = adjv(acc[mf][nf][2]), v3 = adjv(acc[mf][nf][3]);
            a0 += v0 + v2; c0 += v0 * v0 + v2 * v2;
            a1 += v1 + v3; c1 += v1 * v1 + v3 * v3;
        }
        cs[nf * 2] = a0; cq[nf * 2] = c0;
        cs[nf * 2 + 1] = a1; cq[nf * 2 + 1] = c1;
    }
#pragma unroll
    for (int o = 4; o <= 16; o <<= 1)
#pragma unroll
        for (int n = 0; n < 8; n++) {
            cs[n] += __shfl_xor_sync(0xffffffffu, cs[n], o);
            cq[n] += __shfl_xor_sync(0xffffffffu, cq[n], o);
        }
    if (lane < 4) {
#pragma unroll
        for (int n = 0; n < 8; n++) {
            int c = wn + lane * 2 + (n >> 1) * 8 + (n & 1);
            scol[(c * 2 + (wid >> 2)) * 2]     = cs[n];
            scol[(c * 2 + (wid >> 2)) * 2 + 1] = cq[n];
        }
    }
    __syncthreads();
    if (tid < 128) {
        float S = scol[(tid * 2) * 2]     + scol[(tid * 2 + 1) * 2];
        float Q = scol[(tid * 2) * 2 + 1] + scol[(tid * 2 + 1) * 2 + 1];
        float2 v; v.x = S; v.y = Q;
        *(float2*)(g_part + (((size_t)b * 8 + jt) * 8 + it) * 256 + tid * 2) = v;
    }
}

// ---------------------------------------------------------------------------
// K_stats: finalize mu/rstd per output row from the 8 partial slots.
// ---------------------------------------------------------------------------
__global__ void k_stats()
{
    int row = blockIdx.x * 256 + threadIdx.x;
    int blk = row >> 7, rowin = row & 127;
    const float* p = g_part + (size_t)blk * 8 * 256 + rowin * 2;
    float S = 0.f, Q = 0.f;
#pragma unroll
    for (int s = 0; s < 8; s++) { S += p[s * 256]; Q += p[s * 256 + 1]; }
    float mu = S * (1.0f / N_DIM);
    float var = Q * (1.0f / N_DIM) - mu * mu;
    g_mu[row] = mu;
    g_rstd[row] = rsqrtf(var + 1e-5f);
}

// ---------------------------------------------------------------------------
// K2b: identical mainloop (same f32 S) + fused LN + ReLU + single write.
// Params preloaded before the mainloop; output stores use st.global.cs
// (evict-first) so the 268MB write stream doesn't evict c2 from L2.
// ---------------------------------------------------------------------------
__global__ __launch_bounds__(256, 2) void k2b_write(
    float* __restrict__ out, const float* __restrict__ sg,
    const float* __restrict__ sb)
{
    extern __shared__ __nv_bfloat16 smem[];
    int b = blockIdx.z, tt = blockIdx.x;
    int it = IT_MAP[tt], jt = JT_MAP[tt];
    bool diag = (it == jt);
    int tid = threadIdx.x;

    float* sst = (float*)((char*)smem + SMEM_K2);      // 1024 floats
    if (tid < 128) {
        int iG = it * 128 + tid, jG = jt * 128 + tid;
        int base = b * N_DIM;
        sst[0 * 128 + tid] = g_mu[base + iG];
        sst[1 * 128 + tid] = g_rstd[base + iG];
        sst[2 * 128 + tid] = sg[jG];
        sst[3 * 128 + tid] = sb[jG];
        sst[4 * 128 + tid] = g_mu[base + jG];
        sst[5 * 128 + tid] = g_rstd[base + jG];
        sst[6 * 128 + tid] = sg[iG];
        sst[7 * 128 + tid] = sb[iG];
    }

    float acc[4][4][4];
    k2_mainloop(b, it, jt, diag, smem, acc);
    __syncthreads();    // tiles done; sst visible; ts region reusable

    int wid = tid >> 5, lane = tid & 31;
    int wm = (wid >> 2) * 64, wn = (wid & 3) * 32;
    int il = wm + (lane >> 2), jl = wn + (lane & 3) * 2;

    float* ts = (float*)smem;                          // [128][TSP] staging
    float* ob = out + (size_t)b * N_DIM * N_DIM;

    // direct tile: rows i (stats), cols j (affine)
#pragma unroll
    for (int mf = 0; mf < 4; mf++) {
        int i0 = il + mf * 16;
        float mA = sst[i0], rA = sst[128 + i0];
        float mB = sst[i0 + 8], rB = sst[128 + i0 + 8];
#pragma unroll
        for (int nf = 0; nf < 4; nf++) {
            int j0 = jl + nf * 8;
            float gj0 = sst[256 + j0], bj0 = sst[384 + j0];
            float gj1 = sst[256 + j0 + 1], bj1 = sst[384 + j0 + 1];
            float2 v0, v1;
            v0.x = fmaxf((adjv(acc[mf][nf][0]) - mA) * rA * gj0 + bj0, 0.f);
            v0.y = fmaxf((adjv(acc[mf][nf][1]) - mA) * rA * gj1 + bj1, 0.f);
            v1.x = fmaxf((adjv(acc[mf][nf][2]) - mB) * rB * gj0 + bj0, 0.f);
            v1.y = fmaxf((adjv(acc[mf][nf][3]) - mB) * rB * gj1 + bj1, 0.f);
            size_t iG0 = (size_t)(it * 128 + i0) * N_DIM + jt * 128 + j0;
            stcs2(ob + iG0, v0);
            stcs2(ob + iG0 + 8 * N_DIM, v1);
        }
    }

    if (diag) return;

    // mirror tile: rows j (stats), cols i (affine); normalize, stage, write
#pragma unroll
    for (int mf = 0; mf < 4; mf++) {
        int i0 = il + mf * 16;
        float gi0 = sst[768 + i0], bi0 = sst[896 + i0];
        float gi8 = sst[768 + i0 + 8], bi8 = sst[896 + i0 + 8];
#pragma unroll
        for (int nf = 0; nf < 4; nf++) {
            int j0 = jl + nf * 8;
            float mJ0 = sst[512 + j0], rJ0 = sst[640 + j0];
            float mJ1 = sst[512 + j0 + 1], rJ1 = sst[640 + j0 + 1];
            ts[(j0    ) * TSP + i0    ] =
                fmaxf((adjv(acc[mf][nf][0]) - mJ0) * rJ0 * gi0 + bi0, 0.f);
            ts[(j0 + 1) * TSP + i0    ] =
                fmaxf((adjv(acc[mf][nf][1]) - mJ1) * rJ1 * gi0 + bi0, 0.f);
            ts[(j0    ) * TSP + i0 + 8] =
                fmaxf((adjv(acc[mf][nf][2]) - mJ0) * rJ0 * gi8 + bi8, 0.f);
            ts[(j0 + 1) * TSP + i0 + 8] =
                fmaxf((adjv(acc[mf][nf][3]) - mJ1) * rJ1 * gi8 + bi8, 0.f);
        }
    }
    __syncthreads();

#pragma unroll
    for (int pass = 0; pass < 16; pass++) {
        int r = (tid >> 5) + pass * 8;
        int c4 = (tid & 31) * 4;
        float4 v = *(float4*)&ts[r * TSP + c4];
        stcs4(ob + (size_t)(jt * 128 + r) * N_DIM + it * 128 + c4, v);
    }
}

// ---------------------------------------------------------------------------
extern "C" void kernel_launch(void* const* d_in, const int* in_sizes, int n_in,
                              void* d_out, int out_size)
{
    (void)in_sizes; (void)n_in; (void)out_size;
    const float* x        = (const float*)d_in[0];
    const float* conv_w   = (const float*)d_in[1];
    const float* conv_b   = (const float*)d_in[2];
    const float* time_g   = (const float*)d_in[3];
    const float* time_b   = (const float*)d_in[4];
    const float* static_g = (const float*)d_in[5];
    const float* static_b = (const float*)d_in[6];
    float* out = (float*)d_out;

    cudaFuncSetAttribute(k2a_stats, cudaFuncAttributeMaxDynamicSharedMemorySize,
                         SMEM_K2);
    cudaFuncSetAttribute(k2b_write, cudaFuncAttributeMaxDynamicSharedMemorySize,
                         SMEM_K2B);

    k1_rank<<<NROWS / 16, 256>>>(x, conv_w, conv_b, time_g, time_b);

    dim3 g2(36, 1, 64);
    k2a_stats<<<g2, 256, SMEM_K2>>>();
    k_stats<<<NROWS / 256, 256>>>();
    k2b_write<<<g2, 256, SMEM_K2B>>>(out, static_g, static_b);
}